// round 15
// baseline (speedup 1.0000x reference)
#include <cuda_runtime.h>
#include <cuda_fp16.h>
#include <stdint.h>

#define NN 50000
#define EE 800000
#define C  128
#define SCAN_BLOCKS ((NN + 1023) / 1024)    // 49
#define G1_GRID     ((NN + 31) / 32)        // 1563 gemm blocks (32 rows each)
#define FILLB       ((EE / 4 + 127) / 128)  // 1563 fill blocks @128thr
#define CNT_GRID    ((EE / 4 + 255) / 256)  // 782 count blocks @256thr
#define AGG_GRID    ((NN + 7) / 8)          // 6250

// ---------------- scratch (device globals; no allocation) ----------------
// g_deg zero on entry (zero-init at load; re-zeroed by k_agg2_head each call).
// g_bar is a monotonic ticket counter (never reset; replay-safe).
__device__ __half g_hp[(size_t)NN * C];
__device__ __half g_h1[(size_t)NN * C];
__device__ __half g_W1t[C * C];   // W1 transposed [n][k], fp16
__device__ __half g_W2t[C * C];   // W2 transposed [n][k], fp16
__device__ int    g_deg[NN];
__device__ int    g_rowptr[NN + 1];
__device__ int    g_cnt[NN];
__device__ int    g_srcs[EE];
__device__ int    g_bsum[SCAN_BLOCKS];
__device__ unsigned long long g_bar;

// ---------------- fat kernel 1: degree count + W transposes --------------
__device__ __forceinline__ void transpose_w(const float* __restrict__ W,
                                            __half* __restrict__ Wt) {
    __shared__ float stag[32][132];
    int tid = threadIdx.x;
    for (int k0 = 0; k0 < 128; k0 += 32) {
        #pragma unroll
        for (int i = 0; i < 16; i++) {
            int idx = tid + 256 * i;           // 4096 elements
            int r = idx >> 7, c = idx & 127;
            stag[r][c] = W[(size_t)(k0 + r) * 128 + c];
        }
        __syncthreads();
        if (tid < 128) {
            int n = tid;
            __half2 h[16];
            #pragma unroll
            for (int kk = 0; kk < 16; kk++)
                h[kk] = __floats2half2_rn(stag[2 * kk][n], stag[2 * kk + 1][n]);
            uint4* dst = (uint4*)(Wt + (size_t)n * 128 + k0);
            const uint4* src = (const uint4*)h;
            #pragma unroll
            for (int j = 0; j < 4; j++) dst[j] = src[j];
        }
        __syncthreads();
    }
}

__global__ void k_count_w(const int* __restrict__ ei,
                          const float* __restrict__ W1,
                          const float* __restrict__ W2) {
    if (blockIdx.x < CNT_GRID) {
        int e4 = blockIdx.x * blockDim.x + threadIdx.x;
        if (e4 < EE / 4) {
            int4 d = ((const int4*)(ei + EE))[e4];
            atomicAdd(&g_deg[d.x], 1);
            atomicAdd(&g_deg[d.y], 1);
            atomicAdd(&g_deg[d.z], 1);
            atomicAdd(&g_deg[d.w], 1);
        }
    } else if (blockIdx.x == CNT_GRID) {
        transpose_w(W1, g_W1t);
    } else {
        transpose_w(W2, g_W2t);
    }
}

// ---------------- CSR: single-launch scan with grid barrier --------------
__global__ void k_scan1() {
    __shared__ int wsum[32];
    __shared__ int sb[SCAN_BLOCKS];
    __shared__ int s_off;
    int tid = threadIdx.x;
    int lane = tid & 31, wid = tid >> 5;
    int bid = blockIdx.x;
    int i = bid * 1024 + tid;
    int v = (i < NN) ? g_deg[i] : 0;

    int s = v;
    #pragma unroll
    for (int off = 1; off < 32; off <<= 1) {
        int t = __shfl_up_sync(0xffffffffu, s, off);
        if (lane >= off) s += t;
    }
    if (lane == 31) wsum[wid] = s;
    __syncthreads();
    if (wid == 0) {
        int ws = wsum[lane];
        #pragma unroll
        for (int off = 1; off < 32; off <<= 1) {
            int t = __shfl_up_sync(0xffffffffu, ws, off);
            if (lane >= off) ws += t;
        }
        wsum[lane] = ws;
    }
    __syncthreads();

    int excl = s - v + (wid > 0 ? wsum[wid - 1] : 0);
    int T = wsum[31];

    if (tid == 0) {
        g_bsum[bid] = T;
        __threadfence();
        unsigned long long ticket = atomicAdd(&g_bar, 1ull);
        unsigned long long target =
            (ticket / (unsigned long long)SCAN_BLOCKS + 1ull) *
            (unsigned long long)SCAN_BLOCKS;
        while (*((volatile unsigned long long*)&g_bar) < target) { }
        __threadfence();
    }
    __syncthreads();

    if (tid < SCAN_BLOCKS) sb[tid] = g_bsum[tid];
    __syncthreads();
    if (tid == 0) {
        int sum = 0;
        for (int j = 0; j < bid; j++) sum += sb[j];
        s_off = sum;
    }
    __syncthreads();

    int off = s_off;
    if (i < NN) {
        int rp = excl + off;
        g_rowptr[i] = rp;
        g_cnt[i]    = rp;
    }
    if (bid == SCAN_BLOCKS - 1 && tid == 0)
        g_rowptr[NN] = off + T;
}

// ---------------- FP16 MMA GEMM: 32-row tiles, one sync ------------------
__device__ __forceinline__ void mma_fp16(float* c, unsigned a0, unsigned a1,
                                         unsigned a2, unsigned a3,
                                         unsigned b0, unsigned b1) {
    asm volatile(
        "mma.sync.aligned.m16n8k16.row.col.f32.f16.f16.f32 "
        "{%0,%1,%2,%3}, {%4,%5,%6,%7}, {%8,%9}, {%0,%1,%2,%3};"
        : "+f"(c[0]), "+f"(c[1]), "+f"(c[2]), "+f"(c[3])
        : "r"(a0), "r"(a1), "r"(a2), "r"(a3), "r"(b0), "r"(b1));
}

#define KH 136   // halves per smem row (128 + 8 pad -> conflict-free frags)

template <bool XF32>
__device__ __forceinline__ void gemm32_body(const void* __restrict__ Xin,
                                            const __half* __restrict__ Wt,
                                            __half* __restrict__ out, int bx) {
    __shared__ __half Xs[32 * KH];    //  8.7 KB
    __shared__ __half Ws[128 * KH];   // 34.8 KB

    int tid = threadIdx.x;                 // 128 threads, 4 warps
    int warp = tid >> 5, lane = tid & 31;
    int warp_m = warp >> 1, warp_n = warp & 1;   // 2M x 2N warps
    int lg = lane >> 2, lq = lane & 3;
    int row0 = bx * 32;

    // X tile: 32 rows x 128 k
    {
        int r = tid >> 2, q = tid & 3;
        int grow = row0 + r;
        if (XF32) {
            const float* X = (const float*)Xin;
            #pragma unroll
            for (int j = 0; j < 8; j++) {
                float4 v = make_float4(0.f, 0.f, 0.f, 0.f);
                if (grow < NN)
                    v = ((const float4*)X)[(size_t)grow * 32 + q * 8 + j];
                __half2* p = (__half2*)&Xs[r * KH + q * 32 + j * 4];
                p[0] = __floats2half2_rn(v.x, v.y);
                p[1] = __floats2half2_rn(v.z, v.w);
            }
        } else {
            const __half* X = (const __half*)Xin;
            #pragma unroll
            for (int j = 0; j < 4; j++) {
                uint4 u = make_uint4(0, 0, 0, 0);
                if (grow < NN)
                    u = ((const uint4*)X)[(size_t)grow * 16 + q * 4 + j];
                *(uint4*)&Xs[r * KH + q * 32 + j * 8] = u;
            }
        }
    }
    // Wt tile: 128 n-rows x 128 k (pre-transposed fp16, coalesced)
    #pragma unroll
    for (int i = 0; i < 16; i++) {
        int idx = tid + 128 * i;
        int nrow = idx >> 4, seg = idx & 15;
        uint4 u = ((const uint4*)Wt)[nrow * 16 + seg];
        *(uint4*)&Ws[nrow * KH + seg * 8] = u;
    }
    __syncthreads();

    float acc[8][4];
    #pragma unroll
    for (int nt = 0; nt < 8; nt++)
        #pragma unroll
        for (int k = 0; k < 4; k++) acc[nt][k] = 0.f;

    int mm = warp_m * 16 + lg;
    #pragma unroll
    for (int ks = 0; ks < 8; ks++) {
        int kb = ks * 16;
        unsigned a0 = *(unsigned*)&Xs[mm * KH + kb + 2 * lq];
        unsigned a1 = *(unsigned*)&Xs[(mm + 8) * KH + kb + 2 * lq];
        unsigned a2 = *(unsigned*)&Xs[mm * KH + kb + 8 + 2 * lq];
        unsigned a3 = *(unsigned*)&Xs[(mm + 8) * KH + kb + 8 + 2 * lq];
        #pragma unroll
        for (int nt = 0; nt < 8; nt++) {
            int nn = warp_n * 64 + nt * 8 + lg;
            unsigned b0 = *(unsigned*)&Ws[nn * KH + kb + 2 * lq];
            unsigned b1 = *(unsigned*)&Ws[nn * KH + kb + 8 + 2 * lq];
            mma_fp16(acc[nt], a0, a1, a2, a3, b0, b1);
        }
    }

    // epilogue: scale by rsqrt(deg+1), fp16 out
    int r = row0 + warp_m * 16 + lg;
    float s0 = (r < NN)     ? rsqrtf((float)g_deg[r] + 1.0f)     : 0.f;
    float s1 = (r + 8 < NN) ? rsqrtf((float)g_deg[r + 8] + 1.0f) : 0.f;
    #pragma unroll
    for (int nt = 0; nt < 8; nt++) {
        int cc = warp_n * 64 + nt * 8 + lq * 2;
        if (r < NN)
            *(__half2*)&out[(size_t)r * C + cc] =
                __floats2half2_rn(acc[nt][0] * s0, acc[nt][1] * s0);
        if (r + 8 < NN)
            *(__half2*)&out[(size_t)(r + 8) * C + cc] =
                __floats2half2_rn(acc[nt][2] * s1, acc[nt][3] * s1);
    }
}

// ---------------- fat kernel: GEMM layer1 + CSR fill ----------------
__global__ void __launch_bounds__(128)
k_gemm1_fill(const float* __restrict__ X, const int* __restrict__ ei) {
    if (blockIdx.x < G1_GRID) {
        gemm32_body<true>(X, g_W1t, g_hp, blockIdx.x);
    } else {
        int e4 = (blockIdx.x - G1_GRID) * blockDim.x + threadIdx.x;
        if (e4 < EE / 4) {
            int4 s = ((const int4*)ei)[e4];
            int4 d = ((const int4*)(ei + EE))[e4];
            g_srcs[atomicAdd(&g_cnt[d.x], 1)] = s.x;
            g_srcs[atomicAdd(&g_cnt[d.y], 1)] = s.y;
            g_srcs[atomicAdd(&g_cnt[d.z], 1)] = s.z;
            g_srcs[atomicAdd(&g_cnt[d.w], 1)] = s.w;
        }
    }
}

__global__ void __launch_bounds__(128)
k_gemm_l2() {
    gemm32_body<false>(g_h1, g_W2t, g_hp, blockIdx.x);
}

// ---------------- aggregation: half-warp per edge, uint4 rows -------------
// Warp handles one node from the COMPACT CSR; lanes 0-15 take even edges,
// lanes 16-31 take odd edges. One LDG.128 retires 2 edges per warp-instr.
// HADD2 accumulation (4 instr / edge-pair / lane). Result valid lanes 0-15:
// o[j] = relu(di*sum + bias[col*8+j]), col = lane.
__device__ __forceinline__ void agg_row8(const __half* __restrict__ hp,
                                         const float* __restrict__ bias,
                                         int node, int lane, float* o) {
    int half = lane >> 4, col = lane & 15;
    float di = rsqrtf((float)g_deg[node] + 1.0f);
    int beg = g_rowptr[node], end = g_rowptr[node + 1];
    const int* sp = g_srcs;
    const uint4* hp4 = (const uint4*)hp;

    __half2 z = __floats2half2_rn(0.f, 0.f);
    __half2 A0 = z, A1 = z, A2 = z, A3 = z;
    if (half) {  // half 1 seeds with the self row (h' already dinv-scaled)
        uint4 u = hp4[(size_t)node * 16 + col];
        A0 = *(__half2*)&u.x; A1 = *(__half2*)&u.y;
        A2 = *(__half2*)&u.z; A3 = *(__half2*)&u.w;
    }

    int e = beg + half;
    for (; e + 6 < end; e += 8) {   // 4 loads in flight per half
        int s0 = sp[e], s1 = sp[e + 2], s2 = sp[e + 4], s3 = sp[e + 6];
        uint4 u0 = hp4[(size_t)s0 * 16 + col];
        uint4 u1 = hp4[(size_t)s1 * 16 + col];
        uint4 u2 = hp4[(size_t)s2 * 16 + col];
        uint4 u3 = hp4[(size_t)s3 * 16 + col];
        A0 = __hadd2(A0, *(__half2*)&u0.x); A1 = __hadd2(A1, *(__half2*)&u0.y);
        A2 = __hadd2(A2, *(__half2*)&u0.z); A3 = __hadd2(A3, *(__half2*)&u0.w);
        A0 = __hadd2(A0, *(__half2*)&u1.x); A1 = __hadd2(A1, *(__half2*)&u1.y);
        A2 = __hadd2(A2, *(__half2*)&u1.z); A3 = __hadd2(A3, *(__half2*)&u1.w);
        A0 = __hadd2(A0, *(__half2*)&u2.x); A1 = __hadd2(A1, *(__half2*)&u2.y);
        A2 = __hadd2(A2, *(__half2*)&u2.z); A3 = __hadd2(A3, *(__half2*)&u2.w);
        A0 = __hadd2(A0, *(__half2*)&u3.x); A1 = __hadd2(A1, *(__half2*)&u3.y);
        A2 = __hadd2(A2, *(__half2*)&u3.z); A3 = __hadd2(A3, *(__half2*)&u3.w);
    }
    for (; e < end; e += 2) {
        int s = sp[e];
        uint4 u = hp4[(size_t)s * 16 + col];
        A0 = __hadd2(A0, *(__half2*)&u.x); A1 = __hadd2(A1, *(__half2*)&u.y);
        A2 = __hadd2(A2, *(__half2*)&u.z); A3 = __hadd2(A3, *(__half2*)&u.w);
    }

    float2 f0 = __half22float2(A0), f1 = __half22float2(A1);
    float2 f2 = __half22float2(A2), f3 = __half22float2(A3);
    float f[8] = {f0.x, f0.y, f1.x, f1.y, f2.x, f2.y, f3.x, f3.y};
    #pragma unroll
    for (int j = 0; j < 8; j++)
        f[j] += __shfl_down_sync(0xffffffffu, f[j], 16);

    const float* bp = bias + col * 8;
    #pragma unroll
    for (int j = 0; j < 8; j++)
        o[j] = fmaxf(fmaf(di, f[j], bp[j]), 0.f);
}

__global__ void __launch_bounds__(256, 6)
k_agg_l1(const float* __restrict__ bias) {
    int node = blockIdx.x * (blockDim.x >> 5) + (threadIdx.x >> 5);
    if (node >= NN) return;
    int lane = threadIdx.x & 31;
    float o[8];
    agg_row8(g_hp, bias, node, lane, o);
    if (lane < 16) {
        uint4 u;
        __half2 h0 = __floats2half2_rn(o[0], o[1]);
        __half2 h1 = __floats2half2_rn(o[2], o[3]);
        __half2 h2 = __floats2half2_rn(o[4], o[5]);
        __half2 h3 = __floats2half2_rn(o[6], o[7]);
        u.x = *(unsigned*)&h0; u.y = *(unsigned*)&h1;
        u.z = *(unsigned*)&h2; u.w = *(unsigned*)&h3;
        ((uint4*)g_h1)[(size_t)node * 16 + lane] = u;
    }
}

// agg layer-2 fused with linear head; re-zeroes g_deg for next call.
__global__ void __launch_bounds__(256, 6)
k_agg2_head(const float* __restrict__ bias,
            const float* __restrict__ Wl,
            const float* __restrict__ bl,
            float* __restrict__ out) {
    __shared__ float Wls[C * 10];
    __shared__ float bls[10];
    int tid = threadIdx.x;

    for (int i = tid; i < C * 10; i += blockDim.x) Wls[i] = Wl[i];
    if (tid < 10) bls[tid] = bl[tid];
    __syncthreads();

    int node = blockIdx.x * (blockDim.x >> 5) + (tid >> 5);
    if (node >= NN) return;
    int lane = tid & 31;

    float o[8];
    agg_row8(g_hp, bias, node, lane, o);

    if (lane == 0) g_deg[node] = 0;   // reset for next call (after last read)

    if (lane < 16) {
        int col = lane;
        float pc[10];
        const float* wr = &Wls[(8 * col) * 10];
        #pragma unroll
        for (int c = 0; c < 10; c++) {
            float p = 0.f;
            #pragma unroll
            for (int j = 0; j < 8; j++)
                p = fmaf(o[j], wr[j * 10 + c], p);
            pc[c] = p;
        }
        #pragma unroll
        for (int c = 0; c < 10; c++) {
            #pragma unroll
            for (int off = 8; off > 0; off >>= 1)
                pc[c] += __shfl_down_sync(0x0000ffffu, pc[c], off);
        }
        if (col == 0) {
            #pragma unroll
            for (int c = 0; c < 10; c++)
                out[(size_t)node * 10 + c] = pc[c] + bls[c];
        }
    }
}

// ---------------- launch (kernel launches ONLY; 6 launches) ----------------
extern "C" void kernel_launch(void* const* d_in, const int* in_sizes, int n_in,
                              void* d_out, int out_size) {
    const float* x   = (const float*)d_in[0];
    const int*   ei  = (const int*)d_in[1];
    const float* W1  = (const float*)d_in[2];
    const float* b1  = (const float*)d_in[3];
    const float* W2  = (const float*)d_in[4];
    const float* b2  = (const float*)d_in[5];
    const float* Wl  = (const float*)d_in[6];
    const float* bl  = (const float*)d_in[7];
    float* out = (float*)d_out;

    k_count_w<<<CNT_GRID + 2, 256>>>(ei, W1, W2);        // count + W transposes
    k_scan1<<<SCAN_BLOCKS, 1024>>>();                    // rowptr + cnt
    k_gemm1_fill<<<G1_GRID + FILLB, 128>>>(x, ei);       // gemm1 ‖ fill
    k_agg_l1<<<AGG_GRID, 256>>>(b1);
    k_gemm_l2<<<G1_GRID, 128>>>();
    k_agg2_head<<<AGG_GRID, 256>>>(b2, Wl, bl, out);
}

// round 16
// speedup vs baseline: 1.0980x; 1.0980x over previous
#include <cuda_runtime.h>
#include <cuda_fp16.h>
#include <stdint.h>

#define NN 50000
#define EE 800000
#define C  128
#define SCAN_BLOCKS ((NN + 1023) / 1024)   // 49
#define GEMM_GRID   ((NN + 127) / 128)     // 391
#define FILL_GRID   ((EE / 4 + 255) / 256) // 782

// ---------------- scratch (device globals; no allocation) ----------------
__device__ __half g_hp[(size_t)NN * C];   // h' (dinv-scaled gemm out, fp16)
__device__ __half g_h1[(size_t)NN * C];   // h1 (post agg/relu, fp16)
__device__ int    g_deg[NN];
__device__ float  g_dinv[NN];
__device__ int    g_rowptr[NN + 1];
__device__ int    g_cnt[NN];
__device__ int    g_srcs[EE];
__device__ int    g_bsum[SCAN_BLOCKS];

// ---------------- vector load helpers ----------------
__device__ __forceinline__ float4 ld4v(const float* X, size_t off4) {
    return ((const float4*)X)[off4];
}
__device__ __forceinline__ float4 ld4v(const __half* X, size_t off4) {
    uint2 u = ((const uint2*)X)[off4];
    __half2 a = *(__half2*)&u.x, b = *(__half2*)&u.y;
    float2 fa = __half22float2(a), fb = __half22float2(b);
    return make_float4(fa.x, fa.y, fb.x, fb.y);
}
__device__ __forceinline__ void st4h(__half* out, size_t off4, float4 v) {
    uint2 u;
    __half2 lo = __floats2half2_rn(v.x, v.y);
    __half2 hi = __floats2half2_rn(v.z, v.w);
    u.x = *(unsigned*)&lo; u.y = *(unsigned*)&hi;
    ((uint2*)out)[off4] = u;
}

// ---------------- degree / CSR ----------------
__global__ void k_zero_deg() {
    int i = blockIdx.x * blockDim.x + threadIdx.x;
    if (i < NN) g_deg[i] = 0;
}

__global__ void k_count_deg(const int* __restrict__ ei) {
    int e4 = blockIdx.x * blockDim.x + threadIdx.x;
    if (e4 < EE / 4) {
        int4 d = ((const int4*)(ei + EE))[e4];
        atomicAdd(&g_deg[d.x], 1);
        atomicAdd(&g_deg[d.y], 1);
        atomicAdd(&g_deg[d.z], 1);
        atomicAdd(&g_deg[d.w], 1);
    }
}

// Per-block exclusive scan of g_deg, block sums, fused dinv.
__global__ void k_blockscan() {
    __shared__ int wsum[32];
    int tid = threadIdx.x;
    int lane = tid & 31, wid = tid >> 5;
    int i = blockIdx.x * 1024 + tid;
    int v = (i < NN) ? g_deg[i] : 0;

    if (i < NN) g_dinv[i] = rsqrtf((float)v + 1.0f);

    int s = v;
    #pragma unroll
    for (int off = 1; off < 32; off <<= 1) {
        int t = __shfl_up_sync(0xffffffffu, s, off);
        if (lane >= off) s += t;
    }
    if (lane == 31) wsum[wid] = s;
    __syncthreads();
    if (wid == 0) {
        int ws = wsum[lane];
        #pragma unroll
        for (int off = 1; off < 32; off <<= 1) {
            int t = __shfl_up_sync(0xffffffffu, ws, off);
            if (lane >= off) ws += t;
        }
        wsum[lane] = ws;
    }
    __syncthreads();

    int excl = s - v + (wid > 0 ? wsum[wid - 1] : 0);
    if (i < NN) g_rowptr[i] = excl;
    if (tid == 1023) g_bsum[blockIdx.x] = excl + v;
}

__global__ void k_addoff() {
    __shared__ int sb[SCAN_BLOCKS + 1];
    int tid = threadIdx.x;
    if (tid < SCAN_BLOCKS) sb[tid + 1] = g_bsum[tid];
    __syncthreads();
    if (tid == 0) {
        sb[0] = 0;
        for (int j = 1; j <= SCAN_BLOCKS; j++) sb[j] += sb[j - 1];
    }
    __syncthreads();

    int i = blockIdx.x * blockDim.x + tid;
    if (i < NN) {
        int rp = g_rowptr[i] + sb[i >> 10];
        g_rowptr[i] = rp;
        g_cnt[i]    = rp;
        if (i == NN - 1) g_rowptr[NN] = rp + g_deg[i];
    }
}

// ---------------- FP16 tensor-core GEMM (m16n8k16) -----------------------
__device__ __forceinline__ void mma_fp16(float* c, unsigned a0, unsigned a1,
                                         unsigned a2, unsigned a3,
                                         unsigned b0, unsigned b1) {
    asm volatile(
        "mma.sync.aligned.m16n8k16.row.col.f32.f16.f16.f32 "
        "{%0,%1,%2,%3}, {%4,%5,%6,%7}, {%8,%9}, {%0,%1,%2,%3};"
        : "+f"(c[0]), "+f"(c[1]), "+f"(c[2]), "+f"(c[3])
        : "r"(a0), "r"(a1), "r"(a2), "r"(a3), "r"(b0), "r"(b1));
}

#define KS 72

template <typename Tin>
__device__ __forceinline__ void gemm128_body(const Tin* __restrict__ X,
                                             const float* __restrict__ W,
                                             __half* __restrict__ out,
                                             int n, int bx) {
    __shared__ __half Xs[128 * KS];
    __shared__ __half Wt[128 * KS];

    int tid = threadIdx.x;
    int warp = tid >> 5, lane = tid & 31;
    int warp_m = warp >> 2, warp_n = warp & 3;
    int row0 = bx * 128;
    int lq = lane & 3, lg = lane >> 2;

    float acc[4][4][4];
    #pragma unroll
    for (int mt = 0; mt < 4; mt++)
        #pragma unroll
        for (int nt = 0; nt < 4; nt++)
            #pragma unroll
            for (int k = 0; k < 4; k++) acc[mt][nt][k] = 0.f;

    #pragma unroll
    for (int kc = 0; kc < 2; kc++) {
        #pragma unroll
        for (int i = 0; i < 8; i++) {
            int idx = tid + 256 * i;
            int r = idx >> 4, kq = idx & 15;
            float4 v = make_float4(0.f, 0.f, 0.f, 0.f);
            if (row0 + r < n)
                v = ld4v(X, (size_t)(row0 + r) * 32 + kc * 16 + kq);
            __half2* p = (__half2*)&Xs[r * KS + kq * 4];
            p[0] = __floats2half2_rn(v.x, v.y);
            p[1] = __floats2half2_rn(v.z, v.w);
        }
        #pragma unroll
        for (int i = 0; i < 4; i++) {
            int idx = tid + 256 * i;
            int kp = idx & 31, n4 = idx >> 5;
            int k0 = kc * 64 + kp * 2;
            float4 a = ((const float4*)W)[(size_t)k0 * 32 + n4];
            float4 b = ((const float4*)W)[(size_t)(k0 + 1) * 32 + n4];
            int nb = n4 * 4;
            *(__half2*)&Wt[(nb + 0) * KS + kp * 2] = __floats2half2_rn(a.x, b.x);
            *(__half2*)&Wt[(nb + 1) * KS + kp * 2] = __floats2half2_rn(a.y, b.y);
            *(__half2*)&Wt[(nb + 2) * KS + kp * 2] = __floats2half2_rn(a.z, b.z);
            *(__half2*)&Wt[(nb + 3) * KS + kp * 2] = __floats2half2_rn(a.w, b.w);
        }
        __syncthreads();

        #pragma unroll
        for (int ks = 0; ks < 4; ks++) {
            int kb = ks * 16;
            unsigned b[4][2];
            #pragma unroll
            for (int nt = 0; nt < 4; nt++) {
                int nn = warp_n * 32 + nt * 8 + lg;
                b[nt][0] = *(unsigned*)&Wt[nn * KS + kb + 2 * lq];
                b[nt][1] = *(unsigned*)&Wt[nn * KS + kb + 8 + 2 * lq];
            }
            #pragma unroll
            for (int mt = 0; mt < 4; mt++) {
                int mm = warp_m * 64 + mt * 16 + lg;
                unsigned a0 = *(unsigned*)&Xs[mm * KS + kb + 2 * lq];
                unsigned a1 = *(unsigned*)&Xs[(mm + 8) * KS + kb + 2 * lq];
                unsigned a2 = *(unsigned*)&Xs[mm * KS + kb + 8 + 2 * lq];
                unsigned a3 = *(unsigned*)&Xs[(mm + 8) * KS + kb + 8 + 2 * lq];
                #pragma unroll
                for (int nt = 0; nt < 4; nt++)
                    mma_fp16(acc[mt][nt], a0, a1, a2, a3, b[nt][0], b[nt][1]);
            }
        }
        __syncthreads();
    }

    #pragma unroll
    for (int mt = 0; mt < 4; mt++) {
        int r = row0 + warp_m * 64 + mt * 16 + lg;
        float s0 = (r < n)     ? g_dinv[r]     : 0.f;
        float s1 = (r + 8 < n) ? g_dinv[r + 8] : 0.f;
        #pragma unroll
        for (int nt = 0; nt < 4; nt++) {
            int cc = warp_n * 32 + nt * 8 + lq * 2;
            if (r < n) {
                __half2 h = __floats2half2_rn(acc[mt][nt][0] * s0, acc[mt][nt][1] * s0);
                *(__half2*)&out[(size_t)r * C + cc] = h;
            }
            if (r + 8 < n) {
                __half2 h = __floats2half2_rn(acc[mt][nt][2] * s1, acc[mt][nt][3] * s1);
                *(__half2*)&out[(size_t)(r + 8) * C + cc] = h;
            }
        }
    }
}

// ---------------- fat kernel: GEMM layer1 + fill_csr ----------------
__global__ void k_gemm1_fill(const float* __restrict__ X,
                             const float* __restrict__ W,
                             const int* __restrict__ ei) {
    if (blockIdx.x < GEMM_GRID) {
        gemm128_body(X, W, g_hp, NN, blockIdx.x);
    } else {
        int e4 = (blockIdx.x - GEMM_GRID) * blockDim.x + threadIdx.x;
        if (e4 < EE / 4) {
            int4 s = ((const int4*)ei)[e4];
            int4 d = ((const int4*)(ei + EE))[e4];
            g_srcs[atomicAdd(&g_cnt[d.x], 1)] = s.x;
            g_srcs[atomicAdd(&g_cnt[d.y], 1)] = s.y;
            g_srcs[atomicAdd(&g_cnt[d.z], 1)] = s.z;
            g_srcs[atomicAdd(&g_cnt[d.w], 1)] = s.w;
        }
    }
}

// ---------------- aggregation (round-10 verified body) --------------------
// 4 independent gathers in flight, 2 accumulators; fp32 accumulation.
__device__ __forceinline__ float4 agg_row(const __half* __restrict__ hp,
                                          const float4* __restrict__ b4,
                                          int node, int lane) {
    float di = g_dinv[node];
    int e = g_rowptr[node], end = g_rowptr[node + 1];

    float4 a0 = make_float4(0.f, 0.f, 0.f, 0.f);
    float4 a1 = make_float4(0.f, 0.f, 0.f, 0.f);
    for (; e + 3 < end; e += 4) {
        int s0 = g_srcs[e],     s1 = g_srcs[e + 1];
        int s2 = g_srcs[e + 2], s3 = g_srcs[e + 3];
        float4 v0 = ld4v(hp, (size_t)s0 * 32 + lane);
        float4 v1 = ld4v(hp, (size_t)s1 * 32 + lane);
        float4 v2 = ld4v(hp, (size_t)s2 * 32 + lane);
        float4 v3 = ld4v(hp, (size_t)s3 * 32 + lane);
        a0.x += v0.x + v2.x; a0.y += v0.y + v2.y;
        a0.z += v0.z + v2.z; a0.w += v0.w + v2.w;
        a1.x += v1.x + v3.x; a1.y += v1.y + v3.y;
        a1.z += v1.z + v3.z; a1.w += v1.w + v3.w;
    }
    for (; e < end; e++) {
        float4 v = ld4v(hp, (size_t)g_srcs[e] * 32 + lane);
        a0.x += v.x; a0.y += v.y; a0.z += v.z; a0.w += v.w;
    }
    float4 sv = ld4v(hp, (size_t)node * 32 + lane);  // self
    a0.x += a1.x + sv.x; a0.y += a1.y + sv.y;
    a0.z += a1.z + sv.z; a0.w += a1.w + sv.w;

    float4 b = b4[lane];
    float4 o;
    o.x = fmaxf(fmaf(di, a0.x, b.x), 0.f);
    o.y = fmaxf(fmaf(di, a0.y, b.y), 0.f);
    o.z = fmaxf(fmaf(di, a0.z, b.z), 0.f);
    o.w = fmaxf(fmaf(di, a0.w, b.w), 0.f);
    return o;
}

__global__ void __launch_bounds__(256, 6)
k_agg_l1(const float* __restrict__ bias) {
    int node = blockIdx.x * (blockDim.x >> 5) + (threadIdx.x >> 5);
    if (node >= NN) return;
    int lane = threadIdx.x & 31;
    float4 o = agg_row(g_hp, (const float4*)bias, node, lane);
    st4h(g_h1, (size_t)node * 32 + lane, o);
}

__global__ void k_gemm_l2(const float* __restrict__ W) {
    gemm128_body(g_h1, W, g_hp, NN, blockIdx.x);
}

// agg layer-2 fused with linear head: out[n,10] = h2 @ Wl + bl
__global__ void __launch_bounds__(256, 6)
k_agg2_head(const float* __restrict__ bias,
            const float* __restrict__ Wl,
            const float* __restrict__ bl,
            float* __restrict__ out) {
    __shared__ float Wls[C * 10];
    __shared__ float bls[10];
    int tid = threadIdx.x;
    for (int i = tid; i < C * 10; i += blockDim.x) Wls[i] = Wl[i];
    if (tid < 10) bls[tid] = bl[tid];
    __syncthreads();

    int node = blockIdx.x * (blockDim.x >> 5) + (tid >> 5);
    if (node >= NN) return;
    int lane = tid & 31;

    float4 o = agg_row(g_hp, (const float4*)bias, node, lane);

    float pc[10];
    const float* wr = &Wls[(4 * lane) * 10];
    #pragma unroll
    for (int c = 0; c < 10; c++)
        pc[c] = o.x * wr[c] + o.y * wr[10 + c] + o.z * wr[20 + c] + o.w * wr[30 + c];

    #pragma unroll
    for (int c = 0; c < 10; c++) {
        #pragma unroll
        for (int off = 16; off > 0; off >>= 1)
            pc[c] += __shfl_down_sync(0xffffffffu, pc[c], off);
    }
    if (lane == 0) {
        #pragma unroll
        for (int c = 0; c < 10; c++)
            out[(size_t)node * 10 + c] = pc[c] + bls[c];
    }
}

// ---------------- launch (kernel launches ONLY; 8 launches) ----------------
extern "C" void kernel_launch(void* const* d_in, const int* in_sizes, int n_in,
                              void* d_out, int out_size) {
    const float* x   = (const float*)d_in[0];
    const int*   ei  = (const int*)d_in[1];
    const float* W1  = (const float*)d_in[2];
    const float* b1  = (const float*)d_in[3];
    const float* W2  = (const float*)d_in[4];
    const float* b2  = (const float*)d_in[5];
    const float* Wl  = (const float*)d_in[6];
    const float* bl  = (const float*)d_in[7];
    float* out = (float*)d_out;

    k_zero_deg<<<(NN + 255) / 256, 256>>>();
    k_count_deg<<<FILL_GRID, 256>>>(ei);
    k_blockscan<<<SCAN_BLOCKS, 1024>>>();       // also computes dinv
    k_addoff<<<(NN + 255) / 256, 256>>>();      // finalizes rowptr/cnt

    // GEMM layer 1 overlapped with CSR fill in one launch
    k_gemm1_fill<<<GEMM_GRID + FILL_GRID, 256>>>(x, W1, ei);

    int agg_grid = (NN + 7) / 8;
    k_agg_l1<<<agg_grid, 256>>>(b1);
    k_gemm_l2<<<GEMM_GRID, 256>>>(W2);
    k_agg2_head<<<agg_grid, 256>>>(b2, Wl, bl, out);
}

// round 17
// speedup vs baseline: 1.2150x; 1.1066x over previous
#include <cuda_runtime.h>
#include <cuda_fp16.h>
#include <stdint.h>

#define NN 50000
#define EE 800000
#define C  128
#define SCAN_BLOCKS ((NN + 1023) / 1024)    // 49
#define G_GRID      ((NN + 63) / 64)        // 782 gemm blocks (64 rows each)
#define FILL_GRID   ((EE / 4 + 255) / 256)  // 782
#define CNT_GRID    ((EE / 4 + 255) / 256)  // 782
#define XCONV_GRID  ((NN * C / 8 + 255) / 256)  // 3125
#define AGG_GRID    ((NN + 7) / 8)          // 6250

// ---------------- scratch (device globals; no allocation) ----------------
// g_deg zero on entry: zero-init at load, re-zeroed by k_agg2_head each call.
__device__ __half g_x16[(size_t)NN * C];  // X converted to fp16
__device__ __half g_hp[(size_t)NN * C];   // h' (dinv-scaled gemm out)
__device__ __half g_h1[(size_t)NN * C];   // h1 (post agg/relu)
__device__ __half g_W1t[C * C];           // W1^T [n][k] fp16
__device__ __half g_W2t[C * C];           // W2^T [n][k] fp16
__device__ int    g_deg[NN];
__device__ float  g_dinv[NN];
__device__ int    g_rowptr[NN + 1];
__device__ int    g_cnt[NN];
__device__ int    g_srcs[EE];
__device__ int    g_bsum[SCAN_BLOCKS];

// ---------------- helpers ----------------
__device__ __forceinline__ float4 ld4v(const __half* X, size_t off4) {
    uint2 u = ((const uint2*)X)[off4];
    __half2 a = *(__half2*)&u.x, b = *(__half2*)&u.y;
    float2 fa = __half22float2(a), fb = __half22float2(b);
    return make_float4(fa.x, fa.y, fb.x, fb.y);
}
__device__ __forceinline__ void st4h(__half* out, size_t off4, float4 v) {
    uint2 u;
    __half2 lo = __floats2half2_rn(v.x, v.y);
    __half2 hi = __floats2half2_rn(v.z, v.w);
    u.x = *(unsigned*)&lo; u.y = *(unsigned*)&hi;
    ((uint2*)out)[off4] = u;
}

// ---------------- prep fat kernel: count + X->fp16 + W transposes --------
__device__ __forceinline__ void transpose_w(const float* __restrict__ W,
                                            __half* __restrict__ Wt) {
    __shared__ float stag[32][132];
    int tid = threadIdx.x;
    for (int k0 = 0; k0 < 128; k0 += 32) {
        #pragma unroll
        for (int i = 0; i < 16; i++) {
            int idx = tid + 256 * i;
            int r = idx >> 7, c = idx & 127;
            stag[r][c] = W[(size_t)(k0 + r) * 128 + c];
        }
        __syncthreads();
        if (tid < 128) {
            int n = tid;
            __half2 h[16];
            #pragma unroll
            for (int kk = 0; kk < 16; kk++)
                h[kk] = __floats2half2_rn(stag[2 * kk][n], stag[2 * kk + 1][n]);
            uint4* dst = (uint4*)(Wt + (size_t)n * 128 + k0);
            const uint4* src = (const uint4*)h;
            #pragma unroll
            for (int j = 0; j < 4; j++) dst[j] = src[j];
        }
        __syncthreads();
    }
}

__global__ void k_prep(const int* __restrict__ ei, const float* __restrict__ x,
                       const float* __restrict__ W1, const float* __restrict__ W2) {
    int b = blockIdx.x;
    if (b < CNT_GRID) {
        int e4 = b * blockDim.x + threadIdx.x;
        if (e4 < EE / 4) {
            int4 d = ((const int4*)(ei + EE))[e4];
            atomicAdd(&g_deg[d.x], 1);
            atomicAdd(&g_deg[d.y], 1);
            atomicAdd(&g_deg[d.z], 1);
            atomicAdd(&g_deg[d.w], 1);
        }
    } else if (b < CNT_GRID + XCONV_GRID) {
        int i = (b - CNT_GRID) * 256 + threadIdx.x;   // one uint4 (8 halves)
        if (i < NN * C / 8) {
            float4 v0 = ((const float4*)x)[(size_t)i * 2];
            float4 v1 = ((const float4*)x)[(size_t)i * 2 + 1];
            uint4 u;
            __half2 h0 = __floats2half2_rn(v0.x, v0.y);
            __half2 h1 = __floats2half2_rn(v0.z, v0.w);
            __half2 h2 = __floats2half2_rn(v1.x, v1.y);
            __half2 h3 = __floats2half2_rn(v1.z, v1.w);
            u.x = *(unsigned*)&h0; u.y = *(unsigned*)&h1;
            u.z = *(unsigned*)&h2; u.w = *(unsigned*)&h3;
            ((uint4*)g_x16)[i] = u;
        }
    } else if (b == CNT_GRID + XCONV_GRID) {
        transpose_w(W1, g_W1t);
    } else {
        transpose_w(W2, g_W2t);
    }
}

// ---------------- CSR scan (proven pair) ----------------
__global__ void k_blockscan() {
    __shared__ int wsum[32];
    int tid = threadIdx.x;
    int lane = tid & 31, wid = tid >> 5;
    int i = blockIdx.x * 1024 + tid;
    int v = (i < NN) ? g_deg[i] : 0;

    if (i < NN) g_dinv[i] = rsqrtf((float)v + 1.0f);

    int s = v;
    #pragma unroll
    for (int off = 1; off < 32; off <<= 1) {
        int t = __shfl_up_sync(0xffffffffu, s, off);
        if (lane >= off) s += t;
    }
    if (lane == 31) wsum[wid] = s;
    __syncthreads();
    if (wid == 0) {
        int ws = wsum[lane];
        #pragma unroll
        for (int off = 1; off < 32; off <<= 1) {
            int t = __shfl_up_sync(0xffffffffu, ws, off);
            if (lane >= off) ws += t;
        }
        wsum[lane] = ws;
    }
    __syncthreads();

    int excl = s - v + (wid > 0 ? wsum[wid - 1] : 0);
    if (i < NN) g_rowptr[i] = excl;
    if (tid == 1023) g_bsum[blockIdx.x] = excl + v;
}

__global__ void k_addoff() {
    __shared__ int sb[SCAN_BLOCKS + 1];
    int tid = threadIdx.x;
    if (tid < SCAN_BLOCKS) sb[tid + 1] = g_bsum[tid];
    __syncthreads();
    if (tid == 0) {
        sb[0] = 0;
        for (int j = 1; j <= SCAN_BLOCKS; j++) sb[j] += sb[j - 1];
    }
    __syncthreads();

    int i = blockIdx.x * blockDim.x + tid;
    if (i < NN) {
        int rp = g_rowptr[i] + sb[i >> 10];
        g_rowptr[i] = rp;
        g_cnt[i]    = rp;
        if (i == NN - 1) g_rowptr[NN] = rp + g_deg[i];
    }
}

// ---------------- cp.async single-wait FP16 GEMM -------------------------
// 64-row tiles, full K=128 resident, XOR-swizzled 16B chunks, ONE sync.
__device__ __forceinline__ void mma_fp16(float* c, unsigned a0, unsigned a1,
                                         unsigned a2, unsigned a3,
                                         unsigned b0, unsigned b1) {
    asm volatile(
        "mma.sync.aligned.m16n8k16.row.col.f32.f16.f16.f32 "
        "{%0,%1,%2,%3}, {%4,%5,%6,%7}, {%8,%9}, {%0,%1,%2,%3};"
        : "+f"(c[0]), "+f"(c[1]), "+f"(c[2]), "+f"(c[3])
        : "r"(a0), "r"(a1), "r"(a2), "r"(a3), "r"(b0), "r"(b1));
}

// half-index of (row r, 16B chunk c) in swizzled tile
__device__ __forceinline__ int sw_off(int r, int c) {
    return r * 128 + ((c ^ (r & 15)) << 3);
}

__device__ __forceinline__ void gemm64_body(const __half* __restrict__ Xin,
                                            const __half* __restrict__ Wt,
                                            __half* __restrict__ out, int bx) {
    __shared__ __half Xs[64 * 128];    // 16 KB
    __shared__ __half Ws[128 * 128];   // 32 KB  (total exactly 48 KB)

    int tid = threadIdx.x;                 // 256 threads, 8 warps
    int warp = tid >> 5, lane = tid & 31;
    int warp_m = warp >> 2, warp_n = warp & 3;   // 2M x 4N
    int lg = lane >> 2, lq = lane & 3;
    int row0 = bx * 64;

    unsigned xs_b = (unsigned)__cvta_generic_to_shared(Xs);
    unsigned ws_b = (unsigned)__cvta_generic_to_shared(Ws);

    // X tile: 64 rows x 16 chunks = 1024 chunk-tasks (4/thread)
    #pragma unroll
    for (int i = 0; i < 4; i++) {
        int idx = tid + 256 * i;
        int r = idx >> 4, ch = idx & 15;
        int grow = row0 + r;
        int so = sw_off(r, ch);
        if (grow < NN) {
            const void* src = Xin + (size_t)grow * 128 + ch * 8;
            asm volatile("cp.async.ca.shared.global [%0], [%1], 16;\n"
                         :: "r"(xs_b + so * 2), "l"(src));
        } else {
            *(uint4*)&Xs[so] = make_uint4(0, 0, 0, 0);
        }
    }
    // W tile: 128 rows x 16 chunks = 2048 (8/thread)
    #pragma unroll
    for (int i = 0; i < 8; i++) {
        int idx = tid + 256 * i;
        int r = idx >> 4, ch = idx & 15;
        const void* src = Wt + (size_t)r * 128 + ch * 8;
        asm volatile("cp.async.ca.shared.global [%0], [%1], 16;\n"
                     :: "r"(ws_b + sw_off(r, ch) * 2), "l"(src));
    }
    asm volatile("cp.async.commit_group;\n");
    asm volatile("cp.async.wait_group 0;\n");
    __syncthreads();

    float acc[2][4][4];
    #pragma unroll
    for (int mt = 0; mt < 2; mt++)
        #pragma unroll
        for (int nt = 0; nt < 4; nt++)
            #pragma unroll
            for (int k = 0; k < 4; k++) acc[mt][nt][k] = 0.f;

    #pragma unroll
    for (int ks = 0; ks < 8; ks++) {
        int c0 = 2 * ks, c1 = c0 + 1;
        unsigned b[4][2];
        #pragma unroll
        for (int nt = 0; nt < 4; nt++) {
            int nn = warp_n * 32 + nt * 8 + lg;
            b[nt][0] = *(unsigned*)&Ws[sw_off(nn, c0) + 2 * lq];
            b[nt][1] = *(unsigned*)&Ws[sw_off(nn, c1) + 2 * lq];
        }
        #pragma unroll
        for (int mt = 0; mt < 2; mt++) {
            int mm = warp_m * 32 + mt * 16 + lg;
            unsigned a0 = *(unsigned*)&Xs[sw_off(mm, c0) + 2 * lq];
            unsigned a1 = *(unsigned*)&Xs[sw_off(mm + 8, c0) + 2 * lq];
            unsigned a2 = *(unsigned*)&Xs[sw_off(mm, c1) + 2 * lq];
            unsigned a3 = *(unsigned*)&Xs[sw_off(mm + 8, c1) + 2 * lq];
            #pragma unroll
            for (int nt = 0; nt < 4; nt++)
                mma_fp16(acc[mt][nt], a0, a1, a2, a3, b[nt][0], b[nt][1]);
        }
    }

    // epilogue: scale by dinv, fp16 out
    #pragma unroll
    for (int mt = 0; mt < 2; mt++) {
        int r = row0 + warp_m * 32 + mt * 16 + lg;
        float s0 = (r < NN)     ? g_dinv[r]     : 0.f;
        float s1 = (r + 8 < NN) ? g_dinv[r + 8] : 0.f;
        #pragma unroll
        for (int nt = 0; nt < 4; nt++) {
            int cc = warp_n * 32 + nt * 8 + lq * 2;
            if (r < NN)
                *(__half2*)&out[(size_t)r * C + cc] =
                    __floats2half2_rn(acc[mt][nt][0] * s0, acc[mt][nt][1] * s0);
            if (r + 8 < NN)
                *(__half2*)&out[(size_t)(r + 8) * C + cc] =
                    __floats2half2_rn(acc[mt][nt][2] * s1, acc[mt][nt][3] * s1);
        }
    }
}

// ---------------- fat kernel: GEMM layer1 + CSR fill ----------------
__global__ void k_gemm1_fill(const int* __restrict__ ei) {
    if (blockIdx.x < G_GRID) {
        gemm64_body(g_x16, g_W1t, g_hp, blockIdx.x);
    } else {
        int e4 = (blockIdx.x - G_GRID) * blockDim.x + threadIdx.x;
        if (e4 < EE / 4) {
            int4 s = ((const int4*)ei)[e4];
            int4 d = ((const int4*)(ei + EE))[e4];
            g_srcs[atomicAdd(&g_cnt[d.x], 1)] = s.x;
            g_srcs[atomicAdd(&g_cnt[d.y], 1)] = s.y;
            g_srcs[atomicAdd(&g_cnt[d.z], 1)] = s.z;
            g_srcs[atomicAdd(&g_cnt[d.w], 1)] = s.w;
        }
    }
}

__global__ void k_gemm_l2() {
    gemm64_body(g_h1, g_W2t, g_hp, blockIdx.x);
}

// ---------------- aggregation (proven round-10/16 body) -------------------
__device__ __forceinline__ float4 agg_row(const __half* __restrict__ hp,
                                          const float4* __restrict__ b4,
                                          int node, int lane) {
    float di = g_dinv[node];
    int e = g_rowptr[node], end = g_rowptr[node + 1];

    float4 a0 = make_float4(0.f, 0.f, 0.f, 0.f);
    float4 a1 = make_float4(0.f, 0.f, 0.f, 0.f);
    for (; e + 3 < end; e += 4) {
        int s0 = g_srcs[e],     s1 = g_srcs[e + 1];
        int s2 = g_srcs[e + 2], s3 = g_srcs[e + 3];
        float4 v0 = ld4v(hp, (size_t)s0 * 32 + lane);
        float4 v1 = ld4v(hp, (size_t)s1 * 32 + lane);
        float4 v2 = ld4v(hp, (size_t)s2 * 32 + lane);
        float4 v3 = ld4v(hp, (size_t)s3 * 32 + lane);
        a0.x += v0.x + v2.x; a0.y += v0.y + v2.y;
        a0.z += v0.z + v2.z; a0.w += v0.w + v2.w;
        a1.x += v1.x + v3.x; a1.y += v1.y + v3.y;
        a1.z += v1.z + v3.z; a1.w += v1.w + v3.w;
    }
    for (; e < end; e++) {
        float4 v = ld4v(hp, (size_t)g_srcs[e] * 32 + lane);
        a0.x += v.x; a0.y += v.y; a0.z += v.z; a0.w += v.w;
    }
    float4 sv = ld4v(hp, (size_t)node * 32 + lane);  // self
    a0.x += a1.x + sv.x; a0.y += a1.y + sv.y;
    a0.z += a1.z + sv.z; a0.w += a1.w + sv.w;

    float4 b = b4[lane];
    float4 o;
    o.x = fmaxf(fmaf(di, a0.x, b.x), 0.f);
    o.y = fmaxf(fmaf(di, a0.y, b.y), 0.f);
    o.z = fmaxf(fmaf(di, a0.z, b.z), 0.f);
    o.w = fmaxf(fmaf(di, a0.w, b.w), 0.f);
    return o;
}

__global__ void __launch_bounds__(256, 6)
k_agg_l1(const float* __restrict__ bias) {
    int node = blockIdx.x * (blockDim.x >> 5) + (threadIdx.x >> 5);
    if (node >= NN) return;
    int lane = threadIdx.x & 31;
    float4 o = agg_row(g_hp, (const float4*)bias, node, lane);
    st4h(g_h1, (size_t)node * 32 + lane, o);
}

// agg layer-2 fused with linear head; re-zeroes g_deg for next call.
__global__ void __launch_bounds__(256, 6)
k_agg2_head(const float* __restrict__ bias,
            const float* __restrict__ Wl,
            const float* __restrict__ bl,
            float* __restrict__ out) {
    __shared__ float Wls[C * 10];
    __shared__ float bls[10];
    int tid = threadIdx.x;
    for (int i = tid; i < C * 10; i += blockDim.x) Wls[i] = Wl[i];
    if (tid < 10) bls[tid] = bl[tid];
    __syncthreads();

    int node = blockIdx.x * (blockDim.x >> 5) + (tid >> 5);
    if (node >= NN) return;
    int lane = tid & 31;

    float4 o = agg_row(g_hp, (const float4*)bias, node, lane);

    if (lane == 0) g_deg[node] = 0;   // reset for next call

    float pc[10];
    const float* wr = &Wls[(4 * lane) * 10];
    #pragma unroll
    for (int c = 0; c < 10; c++)
        pc[c] = o.x * wr[c] + o.y * wr[10 + c] + o.z * wr[20 + c] + o.w * wr[30 + c];

    #pragma unroll
    for (int c = 0; c < 10; c++) {
        #pragma unroll
        for (int off = 16; off > 0; off >>= 1)
            pc[c] += __shfl_down_sync(0xffffffffu, pc[c], off);
    }
    if (lane == 0) {
        #pragma unroll
        for (int c = 0; c < 10; c++)
            out[(size_t)node * 10 + c] = pc[c] + bls[c];
    }
}

// ---------------- launch (kernel launches ONLY; 7 launches) ----------------
extern "C" void kernel_launch(void* const* d_in, const int* in_sizes, int n_in,
                              void* d_out, int out_size) {
    const float* x   = (const float*)d_in[0];
    const int*   ei  = (const int*)d_in[1];
    const float* W1  = (const float*)d_in[2];
    const float* b1  = (const float*)d_in[3];
    const float* W2  = (const float*)d_in[4];
    const float* b2  = (const float*)d_in[5];
    const float* Wl  = (const float*)d_in[6];
    const float* bl  = (const float*)d_in[7];
    float* out = (float*)d_out;

    k_prep<<<CNT_GRID + XCONV_GRID + 2, 256>>>(ei, x, W1, W2);
    k_blockscan<<<SCAN_BLOCKS, 1024>>>();       // also computes dinv
    k_addoff<<<(NN + 255) / 256, 256>>>();      // finalizes rowptr/cnt
    k_gemm1_fill<<<G_GRID + FILL_GRID, 256>>>(ei);  // gemm1 ‖ fill
    k_agg_l1<<<AGG_GRID, 256>>>(b1);
    k_gemm_l2<<<G_GRID, 256>>>();
    k_agg2_head<<<AGG_GRID, 256>>>(b2, Wl, bl, out);
}